// round 12
// baseline (speedup 1.0000x reference)
#include <cuda_runtime.h>
#include <cuda_fp16.h>
#include <cooperative_groups.h>
#include <cstdint>

namespace cg = cooperative_groups;

// Problem constants: N_NODES=100000, INPUT_DIM=16, HIDDEN_DIM=8
#define MAX_NODES 100000
#define IN_DIM 16
#define HID 8

// Per-node projections in fp16. g_PQ[2*n] = P (16B), g_PQ[2*n+1] = Q (16B). 3.2 MB.
__device__ uint4 g_PQ[MAX_NODES * 2];

__device__ __forceinline__ uint32_t tanh2_fast(uint32_t x) {
    uint32_t y;
    asm("tanh.approx.f16x2 %0, %1;" : "=r"(y) : "r"(x));
    return y;
}

// Per-edge math on gathered fp16 records.
__device__ __forceinline__ float edge_compute(uint4 pv, uint4 qv,
                                              float4 w20, float4 w21, float bias) {
    __half2 s0 = __hadd2(*(__half2*)&pv.x, *(__half2*)&qv.x);
    __half2 s1 = __hadd2(*(__half2*)&pv.y, *(__half2*)&qv.y);
    __half2 s2 = __hadd2(*(__half2*)&pv.z, *(__half2*)&qv.z);
    __half2 s3 = __hadd2(*(__half2*)&pv.w, *(__half2*)&qv.w);

    uint32_t t0 = tanh2_fast(*(uint32_t*)&s0);
    uint32_t t1 = tanh2_fast(*(uint32_t*)&s1);
    uint32_t t2 = tanh2_fast(*(uint32_t*)&s2);
    uint32_t t3 = tanh2_fast(*(uint32_t*)&s3);

    float2 f0 = __half22float2(*(__half2*)&t0);
    float2 f1 = __half22float2(*(__half2*)&t1);
    float2 f2 = __half22float2(*(__half2*)&t2);
    float2 f3 = __half22float2(*(__half2*)&t3);

    float acc = bias;
    acc = fmaf(f0.x, w20.x, acc);
    acc = fmaf(f0.y, w20.y, acc);
    acc = fmaf(f1.x, w20.z, acc);
    acc = fmaf(f1.y, w20.w, acc);
    acc = fmaf(f2.x, w21.x, acc);
    acc = fmaf(f2.y, w21.y, acc);
    acc = fmaf(f3.x, w21.z, acc);
    acc = fmaf(f3.y, w21.w, acc);

    float ex = __expf(-acc);
    return __fdividef(1.0f, 1.0f + ex);
}

// Fused cooperative kernel: phase 1 node projection, grid.sync, phase 2 edges.
// min-blocks=6 caps regs at ~42 so the edge phase keeps high occupancy.
__global__ void __launch_bounds__(256, 6)
fused_kernel(const float* __restrict__ x,
             const int*   __restrict__ eidx,   // [2][E] int32
             const float* __restrict__ W1,     // [32][8]
             const float* __restrict__ b1,     // [8]
             const float* __restrict__ W2,     // [8]
             const float* __restrict__ b2,     // [1]
             float* __restrict__ out,
             int n_nodes, int n_edges) {
    cg::grid_group grid = cg::this_grid();

    // ---- Phase 1: node projection (grid-stride) ----
    __shared__ float4 sW[64];
    __shared__ float  sb1[8];
    if (threadIdx.x < 64) sW[threadIdx.x] = ((const float4*)W1)[threadIdx.x];
    if (threadIdx.x < 8)  sb1[threadIdx.x] = b1[threadIdx.x];
    __syncthreads();

    int gstride = gridDim.x * blockDim.x;
    for (int n = blockIdx.x * blockDim.x + threadIdx.x; n < n_nodes; n += gstride) {
        const float4* xr = (const float4*)(x + (size_t)n * IN_DIM);

        float P[HID], Q[HID];
        #pragma unroll
        for (int j = 0; j < HID; j++) { P[j] = sb1[j]; Q[j] = 0.0f; }

        // Process one float4 of x at a time to keep register pressure low.
        #pragma unroll
        for (int i = 0; i < 4; i++) {
            float4 v4 = xr[i];
            float vv[4] = {v4.x, v4.y, v4.z, v4.w};
            #pragma unroll
            for (int kk = 0; kk < 4; kk++) {
                int k = 4*i + kk;
                float4 wt0 = sW[2*k], wt1 = sW[2*k+1];
                float4 wb0 = sW[32 + 2*k], wb1 = sW[32 + 2*k+1];
                float v = vv[kk];
                P[0] = fmaf(v, wt0.x, P[0]); P[1] = fmaf(v, wt0.y, P[1]);
                P[2] = fmaf(v, wt0.z, P[2]); P[3] = fmaf(v, wt0.w, P[3]);
                P[4] = fmaf(v, wt1.x, P[4]); P[5] = fmaf(v, wt1.y, P[5]);
                P[6] = fmaf(v, wt1.z, P[6]); P[7] = fmaf(v, wt1.w, P[7]);
                Q[0] = fmaf(v, wb0.x, Q[0]); Q[1] = fmaf(v, wb0.y, Q[1]);
                Q[2] = fmaf(v, wb0.z, Q[2]); Q[3] = fmaf(v, wb0.w, Q[3]);
                Q[4] = fmaf(v, wb1.x, Q[4]); Q[5] = fmaf(v, wb1.y, Q[5]);
                Q[6] = fmaf(v, wb1.z, Q[6]); Q[7] = fmaf(v, wb1.w, Q[7]);
            }
        }

        __half2 ph[4], qh[4];
        #pragma unroll
        for (int j = 0; j < 4; j++) {
            ph[j] = __floats2half2_rn(P[2*j], P[2*j+1]);
            qh[j] = __floats2half2_rn(Q[2*j], Q[2*j+1]);
        }
        uint4 pv, qv;
        pv.x = *(uint32_t*)&ph[0]; pv.y = *(uint32_t*)&ph[1];
        pv.z = *(uint32_t*)&ph[2]; pv.w = *(uint32_t*)&ph[3];
        qv.x = *(uint32_t*)&qh[0]; qv.y = *(uint32_t*)&qh[1];
        qv.z = *(uint32_t*)&qh[2]; qv.w = *(uint32_t*)&qh[3];
        g_PQ[2*n]     = pv;
        g_PQ[2*n + 1] = qv;
    }

    // ---- Driver-guaranteed device-wide barrier ----
    grid.sync();

    // ---- Phase 2: edges (grid-stride, 2 per thread per iter, idx prefetch) ----
    float4 w20 = __ldg((const float4*)W2);
    float4 w21 = __ldg((const float4*)W2 + 1);
    float bias = __ldg(b2);

    int n_pairs = n_edges >> 1;
    int p = blockIdx.x * blockDim.x + threadIdx.x;

    if ((n_edges & 1) && p == 0) {
        int e = n_edges - 1;
        int row = __ldg(eidx + e);
        int col = __ldg(eidx + n_edges + e);
        uint4 pv = __ldg(&g_PQ[2*col]);
        uint4 qv = __ldg(&g_PQ[2*row + 1]);
        out[e] = edge_compute(pv, qv, w20, w21, bias);
    }

    if (p >= n_pairs) return;

    int2 rows = __ldg((const int2*)(eidx) + p);
    int2 cols = __ldg((const int2*)(eidx + n_edges) + p);

    while (true) {
        int p_next = p + gstride;
        bool has_next = p_next < n_pairs;

        uint4 pv0 = __ldg(&g_PQ[2*cols.x]);
        uint4 qv0 = __ldg(&g_PQ[2*rows.x + 1]);
        uint4 pv1 = __ldg(&g_PQ[2*cols.y]);
        uint4 qv1 = __ldg(&g_PQ[2*rows.y + 1]);

        int2 rows_n, cols_n;
        if (has_next) {
            rows_n = __ldg((const int2*)(eidx) + p_next);
            cols_n = __ldg((const int2*)(eidx + n_edges) + p_next);
        }

        float2 res;
        res.x = edge_compute(pv0, qv0, w20, w21, bias);
        res.y = edge_compute(pv1, qv1, w20, w21, bias);
        *(float2*)(out + 2*p) = res;

        if (!has_next) break;
        p = p_next;
        rows = rows_n;
        cols = cols_n;
    }
}

extern "C" void kernel_launch(void* const* d_in, const int* in_sizes, int n_in,
                              void* d_out, int out_size) {
    const float* x    = (const float*)d_in[0];
    const int*   eidx = (const int*)d_in[1];
    const float* W1   = (const float*)d_in[2];
    const float* b1   = (const float*)d_in[3];
    const float* W2   = (const float*)d_in[4];
    const float* b2   = (const float*)d_in[5];
    float*       out  = (float*)d_out;

    int n_nodes = in_sizes[0] / IN_DIM;
    int n_edges = in_sizes[1] / 2;

    // Cooperative launch: grid sized from the occupancy contract, so
    // co-residency is guaranteed by the driver (or the launch errors out).
    int dev = 0;
    cudaGetDevice(&dev);
    int nsm = 0;
    cudaDeviceGetAttribute(&nsm, cudaDevAttrMultiProcessorCount, dev);
    int maxb = 0;
    cudaOccupancyMaxActiveBlocksPerMultiprocessor(&maxb, (const void*)fused_kernel, 256, 0);
    if (maxb < 1) maxb = 1;
    if (maxb > 6) maxb = 6;
    int blocks = nsm * maxb;

    void* args[] = {(void*)&x, (void*)&eidx, (void*)&W1, (void*)&b1,
                    (void*)&W2, (void*)&b2, (void*)&out,
                    (void*)&n_nodes, (void*)&n_edges};
    cudaLaunchCooperativeKernel((const void*)fused_kernel,
                                dim3((unsigned)blocks), dim3(256),
                                args, 0, (cudaStream_t)0);
}

// round 13
// speedup vs baseline: 1.2314x; 1.2314x over previous
#include <cuda_runtime.h>
#include <cuda_fp16.h>
#include <cooperative_groups.h>
#include <cstdint>

namespace cg = cooperative_groups;

// Problem constants: N_NODES=100000, INPUT_DIM=16, HIDDEN_DIM=8
#define MAX_NODES 100000
#define IN_DIM 16
#define HID 8

// Per-node projections in fp16. g_PQ[2*n] = P (16B), g_PQ[2*n+1] = Q (16B). 3.2 MB.
__device__ uint4 g_PQ[MAX_NODES * 2];

__device__ __forceinline__ uint32_t tanh2_fast(uint32_t x) {
    uint32_t y;
    asm("tanh.approx.f16x2 %0, %1;" : "=r"(y) : "r"(x));
    return y;
}

// Per-edge math on gathered fp16 records.
__device__ __forceinline__ float edge_compute(uint4 pv, uint4 qv,
                                              float4 w20, float4 w21, float bias) {
    __half2 s0 = __hadd2(*(__half2*)&pv.x, *(__half2*)&qv.x);
    __half2 s1 = __hadd2(*(__half2*)&pv.y, *(__half2*)&qv.y);
    __half2 s2 = __hadd2(*(__half2*)&pv.z, *(__half2*)&qv.z);
    __half2 s3 = __hadd2(*(__half2*)&pv.w, *(__half2*)&qv.w);

    uint32_t t0 = tanh2_fast(*(uint32_t*)&s0);
    uint32_t t1 = tanh2_fast(*(uint32_t*)&s1);
    uint32_t t2 = tanh2_fast(*(uint32_t*)&s2);
    uint32_t t3 = tanh2_fast(*(uint32_t*)&s3);

    float2 f0 = __half22float2(*(__half2*)&t0);
    float2 f1 = __half22float2(*(__half2*)&t1);
    float2 f2 = __half22float2(*(__half2*)&t2);
    float2 f3 = __half22float2(*(__half2*)&t3);

    float acc = bias;
    acc = fmaf(f0.x, w20.x, acc);
    acc = fmaf(f0.y, w20.y, acc);
    acc = fmaf(f1.x, w20.z, acc);
    acc = fmaf(f1.y, w20.w, acc);
    acc = fmaf(f2.x, w21.x, acc);
    acc = fmaf(f2.y, w21.y, acc);
    acc = fmaf(f3.x, w21.z, acc);
    acc = fmaf(f3.y, w21.w, acc);

    float ex = __expf(-acc);
    return __fdividef(1.0f, 1.0f + ex);
}

// Fused cooperative kernel: phase 1 node projection, grid.sync, phase 2 edges.
// min-blocks=4 -> 64-reg cap: enough for the edge loop (needs ~56), no spills.
__global__ void __launch_bounds__(256, 4)
fused_kernel(const float* __restrict__ x,
             const int*   __restrict__ eidx,   // [2][E] int32
             const float* __restrict__ W1,     // [32][8]
             const float* __restrict__ b1,     // [8]
             const float* __restrict__ W2,     // [8]
             const float* __restrict__ b2,     // [1]
             float* __restrict__ out,
             int n_nodes, int n_edges) {
    cg::grid_group grid = cg::this_grid();

    // ---- Phase 1: node projection (grid-stride) ----
    __shared__ float4 sW[64];
    __shared__ float  sb1[8];
    if (threadIdx.x < 64) sW[threadIdx.x] = ((const float4*)W1)[threadIdx.x];
    if (threadIdx.x < 8)  sb1[threadIdx.x] = b1[threadIdx.x];
    __syncthreads();

    int gstride = gridDim.x * blockDim.x;
    for (int n = blockIdx.x * blockDim.x + threadIdx.x; n < n_nodes; n += gstride) {
        const float4* xr = (const float4*)(x + (size_t)n * IN_DIM);
        float xv[IN_DIM];
        #pragma unroll
        for (int i = 0; i < 4; i++) {
            float4 v = xr[i];
            xv[4*i+0] = v.x; xv[4*i+1] = v.y; xv[4*i+2] = v.z; xv[4*i+3] = v.w;
        }

        float P[HID], Q[HID];
        #pragma unroll
        for (int j = 0; j < HID; j++) { P[j] = sb1[j]; Q[j] = 0.0f; }

        #pragma unroll
        for (int k = 0; k < IN_DIM; k++) {
            float4 wt0 = sW[2*k], wt1 = sW[2*k+1];
            float4 wb0 = sW[32 + 2*k], wb1 = sW[32 + 2*k+1];
            float v = xv[k];
            P[0] = fmaf(v, wt0.x, P[0]); P[1] = fmaf(v, wt0.y, P[1]);
            P[2] = fmaf(v, wt0.z, P[2]); P[3] = fmaf(v, wt0.w, P[3]);
            P[4] = fmaf(v, wt1.x, P[4]); P[5] = fmaf(v, wt1.y, P[5]);
            P[6] = fmaf(v, wt1.z, P[6]); P[7] = fmaf(v, wt1.w, P[7]);
            Q[0] = fmaf(v, wb0.x, Q[0]); Q[1] = fmaf(v, wb0.y, Q[1]);
            Q[2] = fmaf(v, wb0.z, Q[2]); Q[3] = fmaf(v, wb0.w, Q[3]);
            Q[4] = fmaf(v, wb1.x, Q[4]); Q[5] = fmaf(v, wb1.y, Q[5]);
            Q[6] = fmaf(v, wb1.z, Q[6]); Q[7] = fmaf(v, wb1.w, Q[7]);
        }

        __half2 ph[4], qh[4];
        #pragma unroll
        for (int j = 0; j < 4; j++) {
            ph[j] = __floats2half2_rn(P[2*j], P[2*j+1]);
            qh[j] = __floats2half2_rn(Q[2*j], Q[2*j+1]);
        }
        uint4 pv, qv;
        pv.x = *(uint32_t*)&ph[0]; pv.y = *(uint32_t*)&ph[1];
        pv.z = *(uint32_t*)&ph[2]; pv.w = *(uint32_t*)&ph[3];
        qv.x = *(uint32_t*)&qh[0]; qv.y = *(uint32_t*)&qh[1];
        qv.z = *(uint32_t*)&qh[2]; qv.w = *(uint32_t*)&qh[3];
        g_PQ[2*n]     = pv;
        g_PQ[2*n + 1] = qv;
    }

    // ---- Driver-guaranteed device-wide barrier ----
    grid.sync();

    // ---- Phase 2: edges (grid-stride, 2 per thread per iter, idx prefetch) ----
    float4 w20 = __ldg((const float4*)W2);
    float4 w21 = __ldg((const float4*)W2 + 1);
    float bias = __ldg(b2);

    int n_pairs = n_edges >> 1;
    int p = blockIdx.x * blockDim.x + threadIdx.x;

    if ((n_edges & 1) && p == 0) {
        int e = n_edges - 1;
        int row = __ldg(eidx + e);
        int col = __ldg(eidx + n_edges + e);
        uint4 pv = __ldg(&g_PQ[2*col]);
        uint4 qv = __ldg(&g_PQ[2*row + 1]);
        out[e] = edge_compute(pv, qv, w20, w21, bias);
    }

    if (p >= n_pairs) return;

    int2 rows = __ldg((const int2*)(eidx) + p);
    int2 cols = __ldg((const int2*)(eidx + n_edges) + p);

    while (true) {
        int p_next = p + gstride;
        bool has_next = p_next < n_pairs;

        uint4 pv0 = __ldg(&g_PQ[2*cols.x]);
        uint4 qv0 = __ldg(&g_PQ[2*rows.x + 1]);
        uint4 pv1 = __ldg(&g_PQ[2*cols.y]);
        uint4 qv1 = __ldg(&g_PQ[2*rows.y + 1]);

        int2 rows_n, cols_n;
        if (has_next) {
            rows_n = __ldg((const int2*)(eidx) + p_next);
            cols_n = __ldg((const int2*)(eidx + n_edges) + p_next);
        }

        float2 res;
        res.x = edge_compute(pv0, qv0, w20, w21, bias);
        res.y = edge_compute(pv1, qv1, w20, w21, bias);
        *(float2*)(out + 2*p) = res;

        if (!has_next) break;
        p = p_next;
        rows = rows_n;
        cols = cols_n;
    }
}

extern "C" void kernel_launch(void* const* d_in, const int* in_sizes, int n_in,
                              void* d_out, int out_size) {
    const float* x    = (const float*)d_in[0];
    const int*   eidx = (const int*)d_in[1];
    const float* W1   = (const float*)d_in[2];
    const float* b1   = (const float*)d_in[3];
    const float* W2   = (const float*)d_in[4];
    const float* b2   = (const float*)d_in[5];
    float*       out  = (float*)d_out;

    int n_nodes = in_sizes[0] / IN_DIM;
    int n_edges = in_sizes[1] / 2;

    // Cooperative launch: grid sized from the occupancy contract, so
    // co-residency is guaranteed by the driver (or the launch errors out).
    int dev = 0;
    cudaGetDevice(&dev);
    int nsm = 0;
    cudaDeviceGetAttribute(&nsm, cudaDevAttrMultiProcessorCount, dev);
    int maxb = 0;
    cudaOccupancyMaxActiveBlocksPerMultiprocessor(&maxb, (const void*)fused_kernel, 256, 0);
    if (maxb < 1) maxb = 1;
    if (maxb > 4) maxb = 4;
    int blocks = nsm * maxb;

    void* args[] = {(void*)&x, (void*)&eidx, (void*)&W1, (void*)&b1,
                    (void*)&W2, (void*)&b2, (void*)&out,
                    (void*)&n_nodes, (void*)&n_edges};
    cudaLaunchCooperativeKernel((const void*)fused_kernel,
                                dim3((unsigned)blocks), dim3(256),
                                args, 0, (cudaStream_t)0);
}

// round 14
// speedup vs baseline: 2.1614x; 1.7552x over previous
#include <cuda_runtime.h>
#include <cuda_fp16.h>
#include <cstdint>

// Problem constants: N_NODES=100000, INPUT_DIM=16, HIDDEN_DIM=8
#define MAX_NODES 100000
#define IN_DIM 16
#define HID 8

// Per-node projections in fp16. g_PQ[2*n] = P (16B), g_PQ[2*n+1] = Q (16B). 3.2 MB.
__device__ uint4 g_PQ[MAX_NODES * 2];

__device__ __forceinline__ uint32_t tanh2_fast(uint32_t x) {
    uint32_t y;
    asm("tanh.approx.f16x2 %0, %1;" : "=r"(y) : "r"(x));
    return y;
}

// Kernel 1: per-node projection. P[n][j] = sum_k x[n][k]*W1[k][j] + b1[j]
//           Q[n][j] = sum_k x[n][k]*W1[16+k][j]
__global__ void node_proj_kernel(const float* __restrict__ x,
                                 const float* __restrict__ W1,   // [32][8]
                                 const float* __restrict__ b1,   // [8]
                                 int n_nodes) {
    __shared__ float4 sW[64];
    __shared__ float  sb1[8];
    if (threadIdx.x < 64) sW[threadIdx.x] = ((const float4*)W1)[threadIdx.x];
    if (threadIdx.x < 8)  sb1[threadIdx.x] = b1[threadIdx.x];
    __syncthreads();

    int n = blockIdx.x * blockDim.x + threadIdx.x;
    if (n >= n_nodes) return;

    const float4* xr = (const float4*)(x + (size_t)n * IN_DIM);
    float xv[IN_DIM];
    #pragma unroll
    for (int i = 0; i < 4; i++) {
        float4 v = xr[i];
        xv[4*i+0] = v.x; xv[4*i+1] = v.y; xv[4*i+2] = v.z; xv[4*i+3] = v.w;
    }

    float P[HID], Q[HID];
    #pragma unroll
    for (int j = 0; j < HID; j++) { P[j] = sb1[j]; Q[j] = 0.0f; }

    #pragma unroll
    for (int k = 0; k < IN_DIM; k++) {
        float4 wt0 = sW[2*k], wt1 = sW[2*k+1];
        float4 wb0 = sW[32 + 2*k], wb1 = sW[32 + 2*k+1];
        float v = xv[k];
        P[0] = fmaf(v, wt0.x, P[0]); P[1] = fmaf(v, wt0.y, P[1]);
        P[2] = fmaf(v, wt0.z, P[2]); P[3] = fmaf(v, wt0.w, P[3]);
        P[4] = fmaf(v, wt1.x, P[4]); P[5] = fmaf(v, wt1.y, P[5]);
        P[6] = fmaf(v, wt1.z, P[6]); P[7] = fmaf(v, wt1.w, P[7]);
        Q[0] = fmaf(v, wb0.x, Q[0]); Q[1] = fmaf(v, wb0.y, Q[1]);
        Q[2] = fmaf(v, wb0.z, Q[2]); Q[3] = fmaf(v, wb0.w, Q[3]);
        Q[4] = fmaf(v, wb1.x, Q[4]); Q[5] = fmaf(v, wb1.y, Q[5]);
        Q[6] = fmaf(v, wb1.z, Q[6]); Q[7] = fmaf(v, wb1.w, Q[7]);
    }

    __half2 ph[4], qh[4];
    #pragma unroll
    for (int j = 0; j < 4; j++) {
        ph[j] = __floats2half2_rn(P[2*j], P[2*j+1]);
        qh[j] = __floats2half2_rn(Q[2*j], Q[2*j+1]);
    }
    uint4 pv, qv;
    pv.x = *(uint32_t*)&ph[0]; pv.y = *(uint32_t*)&ph[1];
    pv.z = *(uint32_t*)&ph[2]; pv.w = *(uint32_t*)&ph[3];
    qv.x = *(uint32_t*)&qh[0]; qv.y = *(uint32_t*)&qh[1];
    qv.z = *(uint32_t*)&qh[2]; qv.w = *(uint32_t*)&qh[3];
    g_PQ[2*n]     = pv;
    g_PQ[2*n + 1] = qv;
}

// Per-edge math on gathered fp16 records.
__device__ __forceinline__ float edge_compute(uint4 pv, uint4 qv,
                                              float4 w20, float4 w21, float bias) {
    __half2 s0 = __hadd2(*(__half2*)&pv.x, *(__half2*)&qv.x);
    __half2 s1 = __hadd2(*(__half2*)&pv.y, *(__half2*)&qv.y);
    __half2 s2 = __hadd2(*(__half2*)&pv.z, *(__half2*)&qv.z);
    __half2 s3 = __hadd2(*(__half2*)&pv.w, *(__half2*)&qv.w);

    uint32_t t0 = tanh2_fast(*(uint32_t*)&s0);
    uint32_t t1 = tanh2_fast(*(uint32_t*)&s1);
    uint32_t t2 = tanh2_fast(*(uint32_t*)&s2);
    uint32_t t3 = tanh2_fast(*(uint32_t*)&s3);

    float2 f0 = __half22float2(*(__half2*)&t0);
    float2 f1 = __half22float2(*(__half2*)&t1);
    float2 f2 = __half22float2(*(__half2*)&t2);
    float2 f3 = __half22float2(*(__half2*)&t3);

    float acc = bias;
    acc = fmaf(f0.x, w20.x, acc);
    acc = fmaf(f0.y, w20.y, acc);
    acc = fmaf(f1.x, w20.z, acc);
    acc = fmaf(f1.y, w20.w, acc);
    acc = fmaf(f2.x, w21.x, acc);
    acc = fmaf(f2.y, w21.y, acc);
    acc = fmaf(f3.x, w21.z, acc);
    acc = fmaf(f3.y, w21.w, acc);

    float ex = __expf(-acc);
    return __fdividef(1.0f, 1.0f + ex);
}

// Kernel 2: persistent grid-stride, 2 edges/thread/iter, next-iter index prefetch.
// Best-measured edge variant (29.95us, 32 regs, 85% occ).
__global__ void __launch_bounds__(256)
edge_kernel_gs(const int* __restrict__ eidx,  // [2][E] int32
               const float* __restrict__ W2,  // [8]
               const float* __restrict__ b2,  // [1]
               float* __restrict__ out,
               int n_edges) {
    int n_pairs = n_edges >> 1;
    int stride = gridDim.x * blockDim.x;
    int p = blockIdx.x * blockDim.x + threadIdx.x;

    float4 w20 = __ldg((const float4*)W2);
    float4 w21 = __ldg((const float4*)W2 + 1);
    float bias = __ldg(b2);

    // Handle odd trailing edge (thread 0 only).
    if ((n_edges & 1) && p == 0) {
        int e = n_edges - 1;
        int row = __ldg(eidx + e);
        int col = __ldg(eidx + n_edges + e);
        uint4 pv = __ldg(&g_PQ[2*col]);
        uint4 qv = __ldg(&g_PQ[2*row + 1]);
        out[e] = edge_compute(pv, qv, w20, w21, bias);
    }

    if (p >= n_pairs) return;

    int2 rows = __ldg((const int2*)(eidx) + p);
    int2 cols = __ldg((const int2*)(eidx + n_edges) + p);

    while (true) {
        int p_next = p + stride;
        bool has_next = p_next < n_pairs;

        uint4 pv0 = __ldg(&g_PQ[2*cols.x]);
        uint4 qv0 = __ldg(&g_PQ[2*rows.x + 1]);
        uint4 pv1 = __ldg(&g_PQ[2*cols.y]);
        uint4 qv1 = __ldg(&g_PQ[2*rows.y + 1]);

        int2 rows_n, cols_n;
        if (has_next) {
            rows_n = __ldg((const int2*)(eidx) + p_next);
            cols_n = __ldg((const int2*)(eidx + n_edges) + p_next);
        }

        float2 res;
        res.x = edge_compute(pv0, qv0, w20, w21, bias);
        res.y = edge_compute(pv1, qv1, w20, w21, bias);
        *(float2*)(out + 2*p) = res;

        if (!has_next) break;
        p = p_next;
        rows = rows_n;
        cols = cols_n;
    }
}

extern "C" void kernel_launch(void* const* d_in, const int* in_sizes, int n_in,
                              void* d_out, int out_size) {
    const float* x    = (const float*)d_in[0];
    const int*   eidx = (const int*)d_in[1];
    const float* W1   = (const float*)d_in[2];
    const float* b1   = (const float*)d_in[3];
    const float* W2   = (const float*)d_in[4];
    const float* b2   = (const float*)d_in[5];
    float*       out  = (float*)d_out;

    int n_nodes = in_sizes[0] / IN_DIM;
    int n_edges = in_sizes[1] / 2;

    {
        int threads = 256;
        int blocks = (n_nodes + threads - 1) / threads;
        node_proj_kernel<<<blocks, threads>>>(x, W1, b1, n_nodes);
    }
    {
        int threads = 256;
        int n_pairs = n_edges / 2;
        int blocks = 148 * 8;   // persistent-ish: ~5 iterations per thread
        int max_blocks = (n_pairs + threads - 1) / threads;
        if (blocks > max_blocks) blocks = max_blocks;
        edge_kernel_gs<<<blocks, threads>>>(eidx, W2, b2, out, n_edges);
    }
}